// round 12
// baseline (speedup 1.0000x reference)
#include <cuda_runtime.h>
#include <cuda_fp16.h>
#include <cstdint>

// ---------------- problem constants ----------------
constexpr int B   = 128;
constexpr int N   = 4096;
constexpr int OUT = 64;
constexpr int F1 = 64, F2 = 128, F3 = 256;

constexpr int TILE  = 128;          // points per work item
constexpr int MAXT  = N / TILE;     // 32
constexpr int MAXW  = B * MAXT;     // 4096 work items
constexpr int GRID  = 152;          // persistent CTAs
constexpr int NT    = 384;          // 8 MMA warps + 4 FFMA warps

constexpr int S3H = 136;            // h2 / wt3 rows (halves, k-dim 128, +8 pad)
constexpr int S3W = S3H / 2;        // 68 words
constexpr int S1F = 66;             // h1f row stride (floats, k-dim 64, +2 pad)
constexpr int S2F = 132;            // w2s row stride (floats, n-dim 128, +4 pad)

__device__ float g_agg[B * F3];
__device__ int   g_work;
__device__ __align__(16) __half wt3g[F3 * S3H];   // [256 n][136 k] fp16

// ---------------- smem layout (bytes) ----------------
constexpr int OFF_W1  = 0;                         // 128 floats
constexpr int OFF_B1  = 512;                       // 64 floats
constexpr int OFF_POP = 768;                       // 8 ints (4-slot ring: w,len)
constexpr int OFF_W2S = 1024;                      // 64*132*4 = 33792
constexpr int OFF_H1F = OFF_W2S + 64 * S2F * 4;    // 34816: 128*66*4 = 33792
constexpr int OFF_H2  = OFF_H1F + TILE * S1F * 4;  // 68608
constexpr int H2B     = TILE * S3H * 2;            // 34816 per buffer
constexpr int SMEM_TOTAL = OFF_H2 + 2 * H2B;       // 138240 B

__device__ __forceinline__ void mma_f16(float* d,
                                        uint32_t a0, uint32_t a1, uint32_t a2, uint32_t a3,
                                        uint32_t b0, uint32_t b1) {
    asm volatile(
        "mma.sync.aligned.m16n8k16.row.col.f32.f16.f16.f32 "
        "{%0,%1,%2,%3}, {%4,%5,%6,%7}, {%8,%9}, {%0,%1,%2,%3};"
        : "+f"(d[0]), "+f"(d[1]), "+f"(d[2]), "+f"(d[3])
        : "r"(a0), "r"(a1), "r"(a2), "r"(a3), "r"(b0), "r"(b1));
}

__device__ __forceinline__ void ldsm4(uint32_t& r0, uint32_t& r1, uint32_t& r2, uint32_t& r3,
                                      uint32_t saddr) {
    asm volatile("ldmatrix.sync.aligned.m8n8.x4.shared.b16 {%0,%1,%2,%3}, [%4];"
                 : "=r"(r0), "=r"(r1), "=r"(r2), "=r"(r3) : "r"(saddr));
}

__device__ __forceinline__ uint32_t packh2(float lo, float hi) {
    __half2 h = __floats2half2_rn(lo, hi);
    return *reinterpret_cast<uint32_t*>(&h);
}
__device__ __forceinline__ unsigned long long pk2(float lo, float hi) {
    unsigned long long d;
    asm("mov.b64 %0, {%1, %2};" : "=l"(d) : "f"(lo), "f"(hi));
    return d;
}
__device__ __forceinline__ unsigned long long dup2(float v) {
    unsigned long long d;
    asm("mov.b64 %0, {%1, %1};" : "=l"(d) : "f"(v));
    return d;
}
__device__ __forceinline__ void fma2(unsigned long long& d, unsigned long long a,
                                     unsigned long long b) {
    asm("fma.rn.f32x2 %0, %1, %2, %0;" : "+l"(d) : "l"(a), "l"(b));
}
__device__ __forceinline__ void unpk2(float& lo, float& hi, unsigned long long v) {
    asm("mov.b64 {%0, %1}, %2;" : "=f"(lo), "=f"(hi) : "l"(v));
}
__device__ __forceinline__ uint32_t smem_u32(const void* p) {
    uint32_t a;
    asm("{ .reg .u64 t; cvta.to.shared.u64 t, %1; cvt.u32.u64 %0, t; }" : "=r"(a) : "l"(p));
    return a;
}

// ---------------- prep: reset counter/agg + convert w3 to fp16 ----------------
__global__ void prep_kernel(const float* __restrict__ w3) {
    int i = blockIdx.x * 256 + threadIdx.x;
    if (i == 0) g_work = 0;
    if (i < B * F3) g_agg[i] = 0.0f;
    if (i < F2 * F3) {           // w3: [128 k][256 n] -> wt3g[n][k]
        int k = i >> 8, n = i & 255;
        wt3g[n * S3H + k] = __float2half_rn(w3[i]);
    }
}

// ---------------- phi: persistent, warp-specialized FFMA/HMMA ----------------
__global__ void __launch_bounds__(NT, 1)
phi_mma_kernel(const float* __restrict__ points, const int* __restrict__ lengths,
               const float* __restrict__ w1, const float* __restrict__ b1,
               const float* __restrict__ w2, const float* __restrict__ b2,
               const float* __restrict__ b3)
{
    extern __shared__ char smem[];
    float* w1s  = reinterpret_cast<float*>(smem + OFF_W1);
    float* b1s  = reinterpret_cast<float*>(smem + OFF_B1);
    int*   spop = reinterpret_cast<int*>(smem + OFF_POP);
    float* w2s  = reinterpret_cast<float*>(smem + OFF_W2S);
    float* h1f  = reinterpret_cast<float*>(smem + OFF_H1F);
    const uint32_t sb = smem_u32(smem);

    const int tid  = threadIdx.x;
    const int lane = tid & 31;
    const int wid  = tid >> 5;         // 0..11

    // ---- staging: small params + w2 (fp32) into smem ----
    if (tid < 128) w1s[tid] = w1[tid];
    else if (tid < 192) b1s[tid - 128] = b1[tid - 128];
    for (int i = tid; i < F1 * F2; i += NT) {
        int k = i >> 7, n = i & 127;
        w2s[k * S2F + n] = w2[i];
    }

    // ---- tid 256 (first FFMA thread) pops work, skipping invalid items ----
    auto pop = [&](int slot) {
        int ww = atomicAdd(&g_work, 1);
        int ll = 0;
        while (ww < MAXW) {
            ll = lengths[ww & (B - 1)];
            if ((ww >> 7) * TILE < ll) break;
            ww = atomicAdd(&g_work, 1);
        }
        spop[slot * 2] = ww; spop[slot * 2 + 1] = ll;
    };

    // ================= role setup =================
    // MMA warps (wid 0..7)
    const int g   = lane >> 2;         // row group 0..7
    const int c   = lane & 3;          // col-in-group 0..3
    const int nb3 = (wid & 7) * 32;    // L3 n-slice

    uint32_t b3r[4][8][2];
    float bb3[4][2];
    if (wid < 8) {
        const uint32_t* w3w = reinterpret_cast<const uint32_t*>(wt3g);
#pragma unroll
        for (int nt = 0; nt < 4; nt++) {
#pragma unroll
            for (int ks = 0; ks < 8; ks++) {
                const int base = (nb3 + nt * 8 + g) * S3W + ks * 8 + c;
                b3r[nt][ks][0] = w3w[base];
                b3r[nt][ks][1] = w3w[base + 4];
            }
            bb3[nt][0] = b3[nb3 + nt * 8 + 2 * c];
            bb3[nt][1] = b3[nb3 + nt * 8 + 2 * c + 1];
        }
    }
    // ldmatrix lane base (both h2 buffers)
    const int tsel = lane >> 3, rr = lane & 7;
    const int lrow = (tsel & 1) * 8 + rr;
    const int lcol = (tsel >> 1) * 4;
    const uint32_t a2base0 = sb + OFF_H2 + (lrow * S3W + lcol) * 4;
    const uint32_t a2base1 = a2base0 + H2B;

    // FFMA warps (wid 8..11): thread owns 8n cols x (8m x 2 passes)
    const int ftid = tid - 256;        // 0..127
    const int nblk = ftid & 15;        // 16 n-blocks of 8 cols
    const int mblk = ftid >> 4;        // 8 m-blocks of 8 rows (x2 passes)
    unsigned long long bpk[4];
    if (wid >= 8) {
#pragma unroll
        for (int j = 0; j < 4; j++)
            bpk[j] = pk2(b2[nblk * 8 + 2 * j], b2[nblk * 8 + 2 * j + 1]);
    }

    // ---- FFMA L1: 2 -> 64 fp32 into h1f (1 point per thread) ----
    auto do_L1f = [&](int ww, int ll) {
        const int bm = (ww >> 7) * TILE;
        const int rw = min(TILE, ll - bm);
        if (ftid < rw) {
            float2 pp = reinterpret_cast<const float2*>(points)[
                (long long)(ww & (B - 1)) * N + bm + ftid];
            const float x = pp.x, y = pp.y;
#pragma unroll
            for (int j = 0; j < 32; j++) {
                const int f = 2 * j;
                float v0 = fmaxf(fmaf(x, w1s[f],     fmaf(y, w1s[64 + f],     b1s[f])),     0.0f);
                float v1 = fmaxf(fmaf(x, w1s[f + 1], fmaf(y, w1s[64 + f + 1], b1s[f + 1])), 0.0f);
                *reinterpret_cast<float2*>(&h1f[ftid * S1F + f]) = make_float2(v0, v1);
            }
        }
    };

    // ---- FFMA L2: h1f(fp32) @ w2s -> h2[buf] (fp16), full fp32 math ----
    auto do_L2 = [&](uint32_t* __restrict__ h2b) {
#pragma unroll
        for (int pass = 0; pass < 2; pass++) {
            const int mbase = pass * 64 + mblk * 8;
            unsigned long long acc[8][4];
#pragma unroll
            for (int i = 0; i < 8; i++)
#pragma unroll
                for (int j = 0; j < 4; j++) acc[i][j] = bpk[j];

            for (int k = 0; k < 64; k++) {
                const float4 wa = *reinterpret_cast<const float4*>(&w2s[k * S2F + nblk * 8]);
                const float4 wb = *reinterpret_cast<const float4*>(&w2s[k * S2F + nblk * 8 + 4]);
                unsigned long long wp0 = pk2(wa.x, wa.y), wp1 = pk2(wa.z, wa.w);
                unsigned long long wp2 = pk2(wb.x, wb.y), wp3 = pk2(wb.z, wb.w);
#pragma unroll
                for (int i = 0; i < 8; i++) {
                    const unsigned long long hp = dup2(h1f[(mbase + i) * S1F + k]);
                    fma2(acc[i][0], wp0, hp);
                    fma2(acc[i][1], wp1, hp);
                    fma2(acc[i][2], wp2, hp);
                    fma2(acc[i][3], wp3, hp);
                }
            }
            // epilogue: relu -> fp16 pairs -> STS128
#pragma unroll
            for (int i = 0; i < 8; i++) {
                uint32_t q[4];
#pragma unroll
                for (int j = 0; j < 4; j++) {
                    float lo, hi;
                    unpk2(lo, hi, acc[i][j]);
                    q[j] = packh2(fmaxf(lo, 0.0f), fmaxf(hi, 0.0f));
                }
                *reinterpret_cast<uint4*>(&h2b[(mbase + i) * S3W + nblk * 4]) =
                    make_uint4(q[0], q[1], q[2], q[3]);
            }
        }
    };

    uint32_t* h2buf0 = reinterpret_cast<uint32_t*>(smem + OFF_H2);
    uint32_t* h2buf1 = reinterpret_cast<uint32_t*>(smem + OFF_H2 + H2B);

    // ================= prologue =================
    if (tid == 256) pop(0);
    __syncthreads();                       // w1s/b1s/w2s + slot0 visible
    {
        const int w0 = spop[0], l0 = spop[1];
        if (w0 < MAXW) {
            if (wid >= 8) {
                do_L1f(w0, l0);
                asm volatile("bar.sync 14, 128;" ::: "memory");
                do_L2(h2buf0);
            }
            if (tid == 256) pop(1);
        }
    }
    __syncthreads();                       // h2[0] + slot1 ready

    // ================= main loop =================
    int it = 0;
    for (;;) {
        const int sc = (it & 3), sn = ((it + 1) & 3);
        const int wc = spop[sc * 2];
        if (wc >= MAXW) break;
        const int lc = spop[sc * 2 + 1];
        const int wn = spop[sn * 2], ln = spop[sn * 2 + 1];

        if (wid < 8) {
            // ---- consumer: L3 of item wc from h2[it&1] ----
            const int bidx   = wc & (B - 1);
            const int base_m = (wc >> 7) * TILE;
            const int rows   = min(TILE, lc - base_m);
            const int mfmax  = (rows + 15) >> 4;
            const uint32_t a2b = (it & 1) ? a2base1 : a2base0;

            float rm[4][2] = {{0,0},{0,0},{0,0},{0,0}};
            for (int mf = 0; mf < mfmax; mf++) {
                float acc[4][4];
#pragma unroll
                for (int nt = 0; nt < 4; nt++)
#pragma unroll
                    for (int j = 0; j < 4; j++) acc[nt][j] = 0.0f;
#pragma unroll
                for (int ks = 0; ks < 8; ks++) {
                    uint32_t a0, a1, a2, a3;
                    ldsm4(a0, a1, a2, a3, a2b + (mf * 16 * S3W + ks * 8) * 4);
#pragma unroll
                    for (int nt = 0; nt < 4; nt++)
                        mma_f16(acc[nt], a0, a1, a2, a3, b3r[nt][ks][0], b3r[nt][ks][1]);
                }
                const int r0 = base_m + mf * 16 + g;
                const int r1 = r0 + 8;
                const bool v0 = r0 < lc, v1 = r1 < lc;
#pragma unroll
                for (int nt = 0; nt < 4; nt++) {
                    float x0 = v0 ? fmaxf(acc[nt][0] + bb3[nt][0], 0.0f) : 0.0f;
                    float x1 = v0 ? fmaxf(acc[nt][1] + bb3[nt][1], 0.0f) : 0.0f;
                    float y0 = v1 ? fmaxf(acc[nt][2] + bb3[nt][0], 0.0f) : 0.0f;
                    float y1 = v1 ? fmaxf(acc[nt][3] + bb3[nt][1], 0.0f) : 0.0f;
                    rm[nt][0] = fmaxf(rm[nt][0], fmaxf(x0, y0));
                    rm[nt][1] = fmaxf(rm[nt][1], fmaxf(x1, y1));
                }
            }
#pragma unroll
            for (int nt = 0; nt < 4; nt++) {
#pragma unroll
                for (int j = 0; j < 2; j++) {
                    float v = rm[nt][j];
                    v = fmaxf(v, __shfl_xor_sync(0xFFFFFFFFu, v, 4));
                    v = fmaxf(v, __shfl_xor_sync(0xFFFFFFFFu, v, 8));
                    v = fmaxf(v, __shfl_xor_sync(0xFFFFFFFFu, v, 16));
                    if (g == 0)
                        atomicMax(reinterpret_cast<int*>(
                            &g_agg[bidx * F3 + nb3 + nt * 8 + 2 * c + j]),
                            __float_as_int(v));
                }
            }
        } else {
            // ---- producer: pop item it+2; L1+L2 of item wn into h2[(it+1)&1] ----
            if (tid == 256) pop((it + 2) & 3);
            if (wn < MAXW) {
                do_L1f(wn, ln);
                asm volatile("bar.sync 14, 128;" ::: "memory");
                do_L2((it & 1) ? h2buf0 : h2buf1);
            }
        }
        __syncthreads();    // h2[(it+1)&1] full; h2[it&1] free; slot(it+2) ready
        it++;
    }
}

__global__ void __launch_bounds__(256)
rho_kernel(const float* __restrict__ r1w, const float* __restrict__ r1b,
           const float* __restrict__ r2w, const float* __restrict__ r2b,
           const float* __restrict__ r3w, const float* __restrict__ r3b,
           float* __restrict__ out)
{
    __shared__ float a[256], z1[256], z2[128];
    const int b   = blockIdx.x;
    const int tid = threadIdx.x;

    a[tid] = g_agg[b * F3 + tid];
    __syncthreads();

    float acc = r1b[tid];
#pragma unroll 4
    for (int k = 0; k < 256; k++) acc = fmaf(a[k], r1w[k * 256 + tid], acc);
    z1[tid] = fmaxf(acc, 0.0f);
    __syncthreads();

    if (tid < 128) {
        float acc2 = r2b[tid];
#pragma unroll 4
        for (int k = 0; k < 256; k++) acc2 = fmaf(z1[k], r2w[k * 128 + tid], acc2);
        z2[tid] = fmaxf(acc2, 0.0f);
    }
    __syncthreads();

    if (tid < 64) {
        float acc3 = r3b[tid];
#pragma unroll 4
        for (int k = 0; k < 128; k++) acc3 = fmaf(z2[k], r3w[k * 64 + tid], acc3);
        out[b * OUT + tid] = acc3;
    }
}

// ---------------- launch ----------------
extern "C" void kernel_launch(void* const* d_in, const int* in_sizes, int n_in,
                              void* d_out, int out_size)
{
    (void)in_sizes; (void)n_in; (void)out_size;
    const float* points = (const float*)d_in[0];
    const int*   lengths= (const int*)  d_in[1];
    const float* w1  = (const float*)d_in[2];
    const float* b1  = (const float*)d_in[3];
    const float* w2  = (const float*)d_in[4];
    const float* b2  = (const float*)d_in[5];
    const float* w3  = (const float*)d_in[6];
    const float* b3  = (const float*)d_in[7];
    const float* r1w = (const float*)d_in[8];
    const float* r1b = (const float*)d_in[9];
    const float* r2w = (const float*)d_in[10];
    const float* r2b = (const float*)d_in[11];
    const float* r3w = (const float*)d_in[12];
    const float* r3b = (const float*)d_in[13];

    cudaFuncSetAttribute(phi_mma_kernel,
                         cudaFuncAttributeMaxDynamicSharedMemorySize, SMEM_TOTAL);

    prep_kernel<<<128, 256>>>(w3);
    phi_mma_kernel<<<GRID, NT, SMEM_TOTAL>>>(points, lengths, w1, b1, w2, b2, b3);
    rho_kernel<<<B, 256>>>(r1w, r1b, r2w, r2b, r3w, r3b, (float*)d_out);
}

// round 13
// speedup vs baseline: 1.4083x; 1.4083x over previous
#include <cuda_runtime.h>
#include <cuda_fp16.h>
#include <cstdint>

// ---------------- problem constants ----------------
constexpr int B   = 128;
constexpr int N   = 4096;
constexpr int OUT = 64;
constexpr int F1 = 64, F2 = 128, F3 = 256;

constexpr int TILE  = 256;          // points per work item
constexpr int MAXT  = N / TILE;     // 16
constexpr int MAXW  = B * MAXT;     // 2048 work items
constexpr int GRID  = 152;          // persistent CTAs
constexpr int NT    = 512;          // threads (16 warps)

// half strides with +8 pad -> conflict-free fragment access
constexpr int S1H = 72;             // h1 / wt2 rows (k-dim 64)
constexpr int S3H = 136;            // h2 / wt3 rows (k-dim 128)
constexpr int S1W = S1H / 2;        // 36 words
constexpr int S3W = S3H / 2;        // 68 words

__device__ float g_agg[B * F3];
__device__ int   g_work;
__device__ int   g_done[B];
__device__ __align__(16) __half wt2g[F2 * S1H];   // [128 n][72 k] fp16
__device__ __align__(16) __half wt3g[F3 * S3H];   // [256 n][136 k] fp16

// ---------------- smem layout (bytes) ----------------
constexpr int OFF_W1   = 0;                          // 128 floats
constexpr int OFF_B1   = 512;                        // 64 floats
constexpr int OFF_POP  = 768;                        // 2 ints (w, len)
constexpr int OFF_FLAG = 784;                        // 1 int
constexpr int OFF_RHO  = 1024;                       // 640 floats (a/z1/z2)
constexpr int OFF_H1   = OFF_RHO + 640 * 4;          // 3584
constexpr int OFF_H2   = OFF_H1 + TILE * S1H * 2;    // 40448
constexpr int SMEM_TOTAL = OFF_H2 + TILE * S3H * 2;  // 110080 B

__device__ __forceinline__ void mma_f16(float* d,
                                        uint32_t a0, uint32_t a1, uint32_t a2, uint32_t a3,
                                        uint32_t b0, uint32_t b1) {
    asm volatile(
        "mma.sync.aligned.m16n8k16.row.col.f32.f16.f16.f32 "
        "{%0,%1,%2,%3}, {%4,%5,%6,%7}, {%8,%9}, {%0,%1,%2,%3};"
        : "+f"(d[0]), "+f"(d[1]), "+f"(d[2]), "+f"(d[3])
        : "r"(a0), "r"(a1), "r"(a2), "r"(a3), "r"(b0), "r"(b1));
}

__device__ __forceinline__ void ldsm4(uint32_t& r0, uint32_t& r1, uint32_t& r2, uint32_t& r3,
                                      uint32_t saddr) {
    asm volatile("ldmatrix.sync.aligned.m8n8.x4.shared.b16 {%0,%1,%2,%3}, [%4];"
                 : "=r"(r0), "=r"(r1), "=r"(r2), "=r"(r3) : "r"(saddr));
}

__device__ __forceinline__ uint32_t packh2(float lo, float hi) {
    __half2 h = __floats2half2_rn(lo, hi);
    return *reinterpret_cast<uint32_t*>(&h);
}

__device__ __forceinline__ uint32_t smem_u32(const void* p) {
    uint32_t a;
    asm("{ .reg .u64 t; cvta.to.shared.u64 t, %1; cvt.u32.u64 %0, t; }" : "=r"(a) : "l"(p));
    return a;
}

// ---------------- prep: reset counters/agg + convert weights ----------------
__global__ void prep_kernel(const float* __restrict__ w2, const float* __restrict__ w3) {
    int i = blockIdx.x * 256 + threadIdx.x;
    if (i == 0) g_work = 0;
    if (i < B) g_done[i] = 0;
    if (i < B * F3) g_agg[i] = 0.0f;
    if (i < F1 * F2) {           // w2: [64 k][128 n] -> wt2g[n][k]
        int k = i >> 7, n = i & 127;
        wt2g[n * S1H + k] = __float2half_rn(w2[i]);
    }
    if (i < F2 * F3) {           // w3: [128 k][256 n] -> wt3g[n][k]
        int k = i >> 8, n = i & 255;
        wt3g[n * S3H + k] = __float2half_rn(w3[i]);
    }
}

// ---------------- phi (+fused rho): persistent work-stealing ----------------
__global__ void __launch_bounds__(NT, 1)
phi_mma_kernel(const float* __restrict__ points, const int* __restrict__ lengths,
               const float* __restrict__ w1, const float* __restrict__ b1,
               const float* __restrict__ b2, const float* __restrict__ b3,
               const float* __restrict__ r1w, const float* __restrict__ r1b,
               const float* __restrict__ r2w, const float* __restrict__ r2b,
               const float* __restrict__ r3w, const float* __restrict__ r3b,
               float* __restrict__ out)
{
    extern __shared__ char smem[];
    float* w1s   = reinterpret_cast<float*>(smem + OFF_W1);
    float* b1s   = reinterpret_cast<float*>(smem + OFF_B1);
    int*   spop  = reinterpret_cast<int*>(smem + OFF_POP);
    int*   sflag = reinterpret_cast<int*>(smem + OFF_FLAG);
    float* s_a   = reinterpret_cast<float*>(smem + OFF_RHO);        // 256
    float* s_z1  = s_a + 256;                                        // 256
    float* s_z2  = s_z1 + 256;                                       // 128
    uint32_t* h1w = reinterpret_cast<uint32_t*>(smem + OFF_H1);
    uint32_t* h2w = reinterpret_cast<uint32_t*>(smem + OFF_H2);
    const uint32_t sb = smem_u32(smem);

    const int tid  = threadIdx.x;
    const int lane = tid & 31;
    const int wid  = tid >> 5;         // 0..15
    const int g    = lane >> 2;        // row group 0..7
    const int c    = lane & 3;         // col-in-group 0..3
    const int nb2  = wid * 8;          // L2 n-slice (8 cols)
    const int nb3  = wid * 16;         // L3 n-slice (16 cols)

    if (tid < 128) w1s[tid] = w1[tid];
    else if (tid < 192) b1s[tid - 128] = b1[tid - 128];
    if (tid == 1) *sflag = -1;

    // ---- persistent B fragments + biases (registers) ----
    const uint32_t* w2w = reinterpret_cast<const uint32_t*>(wt2g);
    const uint32_t* w3w = reinterpret_cast<const uint32_t*>(wt3g);
    uint32_t b2r[4][2];
#pragma unroll
    for (int ks = 0; ks < 4; ks++) {
        const int base = (nb2 + g) * S1W + ks * 8 + c;
        b2r[ks][0] = w2w[base];
        b2r[ks][1] = w2w[base + 4];
    }
    uint32_t b3r[2][8][2];
#pragma unroll
    for (int nt = 0; nt < 2; nt++)
#pragma unroll
        for (int ks = 0; ks < 8; ks++) {
            const int base = (nb3 + nt * 8 + g) * S3W + ks * 8 + c;
            b3r[nt][ks][0] = w3w[base];
            b3r[nt][ks][1] = w3w[base + 4];
        }
    float bb2[2], bb3[2][2];
    bb2[0] = b2[nb2 + 2 * c];
    bb2[1] = b2[nb2 + 2 * c + 1];
#pragma unroll
    for (int nt = 0; nt < 2; nt++) {
        bb3[nt][0] = b3[nb3 + nt * 8 + 2 * c];
        bb3[nt][1] = b3[nb3 + nt * 8 + 2 * c + 1];
    }

    // ---- ldmatrix per-lane base addresses ----
    const int tsel = lane >> 3, rr = lane & 7;
    const int lrow = (tsel & 1) * 8 + rr;
    const int lcol = (tsel >> 1) * 4;
    const uint32_t a1base = sb + OFF_H1 + (lrow * S1W + lcol) * 4;
    const uint32_t a2base = sb + OFF_H2 + (lrow * S3W + lcol) * 4;

    // ---- tid0 pop: skip invalid items without CTA barriers ----
    auto pop = [&]() {
        int ww = atomicAdd(&g_work, 1);
        int ll = 0;
        while (ww < MAXW) {
            ll = lengths[ww & (B - 1)];
            if ((ww >> 7) * TILE < ll) break;
            ww = atomicAdd(&g_work, 1);
        }
        spop[0] = ww; spop[1] = ll;
    };

    // ---- L1 compute+store (after points already in regs) ----
    const int p0_ = tid >> 2, cl_ = tid & 3;
    auto l1_store = [&](const float2* preg, int rw) {
#pragma unroll
        for (int hh = 0; hh < 2; hh++) {
            const int p = p0_ + hh * 128;
            if (p < rw) {
                const float x = preg[hh].x, y = preg[hh].y;
#pragma unroll
                for (int i = 0; i < 8; i++) {
                    const int f = 8 * i + 2 * cl_;
                    float v0 = fmaxf(fmaf(x, w1s[f],     fmaf(y, w1s[64 + f],     b1s[f])),     0.0f);
                    float v1 = fmaxf(fmaf(x, w1s[f + 1], fmaf(y, w1s[64 + f + 1], b1s[f + 1])), 0.0f);
                    h1w[p * S1W + 4 * i + cl_] = packh2(v0, v1);
                }
            }
        }
    };
    auto l1_load = [&](int ww, int ll, float2* preg) {
        const int bm = (ww >> 7) * TILE;
        const int rw = min(TILE, ll - bm);
        const int bx = ww & (B - 1);
#pragma unroll
        for (int hh = 0; hh < 2; hh++) {
            const int p = p0_ + hh * 128;
            preg[hh] = (p < rw)
                ? reinterpret_cast<const float2*>(points)[(long long)bx * N + bm + p]
                : make_float2(0.0f, 0.0f);
        }
        return rw;
    };

    // ---- prologue: first item's L1 ----
    if (tid == 0) pop();
    __syncthreads();
    int w = spop[0], len = spop[1];
    if (w < MAXW) {
        float2 preg[2];
        int rw = l1_load(w, len, preg);
        l1_store(preg, rw);
    }
    __syncthreads();    // h1 ready

    while (w < MAXW) {
        const int bidx   = w & (B - 1);
        const int base_m = (w >> 7) * TILE;
        const int rows   = min(TILE, len - base_m);
        const int mfmax  = (rows + 15) >> 4;
        const int tiles  = (len + TILE - 1) >> 8;   // valid tiles for this batch

        // ---- phase B: layer 2 (clipped) + prefetch next work item ----
        for (int mf = 0; mf < mfmax; mf++) {
            float acc[4] = {0.0f, 0.0f, 0.0f, 0.0f};
#pragma unroll
            for (int ks = 0; ks < 4; ks++) {
                uint32_t a0, a1, a2, a3;
                ldsm4(a0, a1, a2, a3, a1base + (mf * 16 * S1W + ks * 8) * 4);
                mma_f16(acc, a0, a1, a2, a3, b2r[ks][0], b2r[ks][1]);
            }
            const int r0 = mf * 16 + g, r1 = r0 + 8;
            const int cw = nb2 / 2 + c;
            h2w[r0 * S3W + cw] = packh2(fmaxf(acc[0] + bb2[0], 0.0f),
                                        fmaxf(acc[1] + bb2[1], 0.0f));
            h2w[r1 * S3W + cw] = packh2(fmaxf(acc[2] + bb2[0], 0.0f),
                                        fmaxf(acc[3] + bb2[1], 0.0f));
        }
        if (tid == 0) pop();
        __syncthreads();    // h2 ready + next item known; L2 done reading h1
        const int wn = spop[0], lenn = spop[1];

        // ---- phase C: issue next-tile point LDGs, L3, flush, then L1 stores ----
        float2 preg[2];
        int rwn = 0;
        if (wn < MAXW) rwn = l1_load(wn, lenn, preg);   // gmem latency hides under L3

        float rm[2][2] = {{0.0f, 0.0f}, {0.0f, 0.0f}};
        for (int mf = 0; mf < mfmax; mf++) {
            float acc[2][4];
#pragma unroll
            for (int nt = 0; nt < 2; nt++)
#pragma unroll
                for (int j = 0; j < 4; j++) acc[nt][j] = 0.0f;
#pragma unroll
            for (int ks = 0; ks < 8; ks++) {
                uint32_t a0, a1, a2, a3;
                ldsm4(a0, a1, a2, a3, a2base + (mf * 16 * S3W + ks * 8) * 4);
#pragma unroll
                for (int nt = 0; nt < 2; nt++)
                    mma_f16(acc[nt], a0, a1, a2, a3, b3r[nt][ks][0], b3r[nt][ks][1]);
            }
            const int r0 = base_m + mf * 16 + g;
            const int r1 = r0 + 8;
            const bool v0 = r0 < len, v1 = r1 < len;
#pragma unroll
            for (int nt = 0; nt < 2; nt++) {
                float x0 = v0 ? fmaxf(acc[nt][0] + bb3[nt][0], 0.0f) : 0.0f;
                float x1 = v0 ? fmaxf(acc[nt][1] + bb3[nt][1], 0.0f) : 0.0f;
                float y0 = v1 ? fmaxf(acc[nt][2] + bb3[nt][0], 0.0f) : 0.0f;
                float y1 = v1 ? fmaxf(acc[nt][3] + bb3[nt][1], 0.0f) : 0.0f;
                rm[nt][0] = fmaxf(rm[nt][0], fmaxf(x0, y0));
                rm[nt][1] = fmaxf(rm[nt][1], fmaxf(x1, y1));
            }
        }
        // flush: per-warp disjoint cols
#pragma unroll
        for (int nt = 0; nt < 2; nt++) {
#pragma unroll
            for (int j = 0; j < 2; j++) {
                float v = rm[nt][j];
                v = fmaxf(v, __shfl_xor_sync(0xFFFFFFFFu, v, 4));
                v = fmaxf(v, __shfl_xor_sync(0xFFFFFFFFu, v, 8));
                v = fmaxf(v, __shfl_xor_sync(0xFFFFFFFFu, v, 16));
                if (g == 0)
                    atomicMax(reinterpret_cast<int*>(&g_agg[bidx * F3 + nb3 + nt * 8 + 2 * c + j]),
                              __float_as_int(v));
            }
        }
        // per-warp arrival: fence own atomicMax, count; last arrival flags rho
        if (lane == 0) {
            __threadfence();
            int d = atomicAdd(&g_done[bidx], 1);
            if (d == 16 * tiles - 1) *sflag = bidx;
        }
        // L1 stores for next tile (h1 free since sync2)
        if (wn < MAXW) l1_store(preg, rwn);

        w = wn; len = lenn;
        __syncthreads();    // h1(next) ready; flag visible; all flushes issued

        // ---- fused rho: CTA that retired the last tile of a batch ----
        const int fb = *sflag;
        if (fb >= 0) {
            if (tid < 256) s_a[tid] = __ldcg(&g_agg[fb * F3 + tid]);
            __syncthreads();
            if (tid < 256) {
                float acc = r1b[tid];
#pragma unroll 4
                for (int k = 0; k < 256; k++) acc = fmaf(s_a[k], r1w[k * 256 + tid], acc);
                s_z1[tid] = fmaxf(acc, 0.0f);
            }
            __syncthreads();
            if (tid < 128) {
                float acc = r2b[tid];
#pragma unroll 4
                for (int k = 0; k < 256; k++) acc = fmaf(s_z1[k], r2w[k * 128 + tid], acc);
                s_z2[tid] = fmaxf(acc, 0.0f);
            }
            __syncthreads();
            if (tid < 64) {
                float acc = r3b[tid];
#pragma unroll 4
                for (int k = 0; k < 128; k++) acc = fmaf(s_z2[k], r3w[k * 64 + tid], acc);
                out[fb * OUT + tid] = acc;
            }
            if (tid == 1) *sflag = -1;
            __syncthreads();    // flag reset + rho smem quiesced
        }
    }
}

// ---------------- launch ----------------
extern "C" void kernel_launch(void* const* d_in, const int* in_sizes, int n_in,
                              void* d_out, int out_size)
{
    (void)in_sizes; (void)n_in; (void)out_size;
    const float* points = (const float*)d_in[0];
    const int*   lengths= (const int*)  d_in[1];
    const float* w1  = (const float*)d_in[2];
    const float* b1  = (const float*)d_in[3];
    const float* w2  = (const float*)d_in[4];
    const float* b2  = (const float*)d_in[5];
    const float* w3  = (const float*)d_in[6];
    const float* b3  = (const float*)d_in[7];
    const float* r1w = (const float*)d_in[8];
    const float* r1b = (const float*)d_in[9];
    const float* r2w = (const float*)d_in[10];
    const float* r2b = (const float*)d_in[11];
    const float* r3w = (const float*)d_in[12];
    const float* r3b = (const float*)d_in[13];

    cudaFuncSetAttribute(phi_mma_kernel,
                         cudaFuncAttributeMaxDynamicSharedMemorySize, SMEM_TOTAL);

    prep_kernel<<<128, 256>>>(w2, w3);
    phi_mma_kernel<<<GRID, NT, SMEM_TOTAL>>>(points, lengths, w1, b1, b2, b3,
                                             r1w, r1b, r2w, r2b, r3w, r3b,
                                             (float*)d_out);
}

// round 14
// speedup vs baseline: 2.0251x; 1.4380x over previous
#include <cuda_runtime.h>
#include <cuda_fp16.h>
#include <cstdint>

// ---------------- problem constants ----------------
constexpr int B   = 128;
constexpr int N   = 4096;
constexpr int OUT = 64;
constexpr int F1 = 64, F2 = 128, F3 = 256;

constexpr int TILE  = 256;          // points per work item
constexpr int MAXT  = N / TILE;     // 16
constexpr int MAXW  = B * MAXT;     // 2048 work items (per half)
constexpr int GRID  = 304;          // 2 CTAs per SM (even=lo half, odd=hi half)
constexpr int NT    = 256;          // 8 warps per CTA

// half strides with +8 pad -> conflict-free fragment access
constexpr int S1H = 72;             // h1 / wt2 rows (k-dim 64)
constexpr int S3H = 136;            // h2 / wt3 rows (k-dim 128)
constexpr int S1W = S1H / 2;        // 36 words
constexpr int S3W = S3H / 2;        // 68 words

__device__ float g_agg[B * F3];
__device__ int   g_work2[2];        // one counter per feature-half
__device__ __align__(16) __half wt2g[F2 * S1H];   // [128 n][72 k] fp16
__device__ __align__(16) __half wt3g[F3 * S3H];   // [256 n][136 k] fp16

// ---------------- smem layout (bytes) ----------------
constexpr int OFF_W1  = 0;                          // 128 floats
constexpr int OFF_B1  = 512;                        // 64 floats
constexpr int OFF_POP = 768;                        // 2 ints (w, len)
constexpr int OFF_H1  = 1024;                       // 256*72 halves = 36864 B
constexpr int OFF_H2  = OFF_H1 + TILE * S1H * 2;    // 37888
constexpr int SMEM_TOTAL = OFF_H2 + TILE * S3H * 2; // 107520 B (x2 CTAs = 215 KB/SM)

__device__ __forceinline__ void mma_f16(float* d,
                                        uint32_t a0, uint32_t a1, uint32_t a2, uint32_t a3,
                                        uint32_t b0, uint32_t b1) {
    asm volatile(
        "mma.sync.aligned.m16n8k16.row.col.f32.f16.f16.f32 "
        "{%0,%1,%2,%3}, {%4,%5,%6,%7}, {%8,%9}, {%0,%1,%2,%3};"
        : "+f"(d[0]), "+f"(d[1]), "+f"(d[2]), "+f"(d[3])
        : "r"(a0), "r"(a1), "r"(a2), "r"(a3), "r"(b0), "r"(b1));
}

__device__ __forceinline__ void ldsm4(uint32_t& r0, uint32_t& r1, uint32_t& r2, uint32_t& r3,
                                      uint32_t saddr) {
    asm volatile("ldmatrix.sync.aligned.m8n8.x4.shared.b16 {%0,%1,%2,%3}, [%4];"
                 : "=r"(r0), "=r"(r1), "=r"(r2), "=r"(r3) : "r"(saddr));
}

__device__ __forceinline__ uint32_t packh2(float lo, float hi) {
    __half2 h = __floats2half2_rn(lo, hi);
    return *reinterpret_cast<uint32_t*>(&h);
}

__device__ __forceinline__ uint32_t smem_u32(const void* p) {
    uint32_t a;
    asm("{ .reg .u64 t; cvta.to.shared.u64 t, %1; cvt.u32.u64 %0, t; }" : "=r"(a) : "l"(p));
    return a;
}

// ---------------- prep: reset counters/agg + convert weights ----------------
__global__ void prep_kernel(const float* __restrict__ w2, const float* __restrict__ w3) {
    int i = blockIdx.x * 256 + threadIdx.x;
    if (i < 2) g_work2[i] = 0;
    if (i < B * F3) g_agg[i] = 0.0f;
    if (i < F1 * F2) {           // w2: [64 k][128 n] -> wt2g[n][k]
        int k = i >> 7, n = i & 127;
        wt2g[n * S1H + k] = __float2half_rn(w2[i]);
    }
    if (i < F2 * F3) {           // w3: [128 k][256 n] -> wt3g[n][k]
        int k = i >> 8, n = i & 255;
        wt3g[n * S3H + k] = __float2half_rn(w3[i]);
    }
}

// ---------------- phi: split-N dual-CTA persistent work-stealing ----------------
__global__ void __launch_bounds__(NT, 2)
phi_mma_kernel(const float* __restrict__ points, const int* __restrict__ lengths,
               const float* __restrict__ w1, const float* __restrict__ b1,
               const float* __restrict__ b2, const float* __restrict__ b3)
{
    extern __shared__ char smem[];
    float* w1s  = reinterpret_cast<float*>(smem + OFF_W1);
    float* b1s  = reinterpret_cast<float*>(smem + OFF_B1);
    int*   spop = reinterpret_cast<int*>(smem + OFF_POP);
    uint32_t* h1w = reinterpret_cast<uint32_t*>(smem + OFF_H1);
    uint32_t* h2w = reinterpret_cast<uint32_t*>(smem + OFF_H2);
    const uint32_t sb = smem_u32(smem);

    const int half = blockIdx.x & 1;    // feature half: 0 -> cols 0-127, 1 -> 128-255
    const int tid  = threadIdx.x;
    const int lane = tid & 31;
    const int wid  = tid >> 5;          // 0..7
    const int g    = lane >> 2;         // row group 0..7
    const int c    = lane & 3;          // col-in-group 0..3
    const int nb2  = wid * 16;          // L2 n-slice (16 cols, 8 warps cover 128)
    const int gb3  = half * 128 + wid * 16;   // L3 global col base (16 cols of this half)

    if (tid < 128) w1s[tid] = w1[tid];
    else if (tid < 192) b1s[tid - 128] = b1[tid - 128];

    // ---- persistent B fragments + biases (registers) ----
    const uint32_t* w2w = reinterpret_cast<const uint32_t*>(wt2g);
    const uint32_t* w3w = reinterpret_cast<const uint32_t*>(wt3g);
    uint32_t b2r[2][4][2];
#pragma unroll
    for (int nt = 0; nt < 2; nt++)
#pragma unroll
        for (int ks = 0; ks < 4; ks++) {
            const int base = (nb2 + nt * 8 + g) * S1W + ks * 8 + c;
            b2r[nt][ks][0] = w2w[base];
            b2r[nt][ks][1] = w2w[base + 4];
        }
    uint32_t b3r[2][8][2];
#pragma unroll
    for (int nt = 0; nt < 2; nt++)
#pragma unroll
        for (int ks = 0; ks < 8; ks++) {
            const int base = (gb3 + nt * 8 + g) * S3W + ks * 8 + c;
            b3r[nt][ks][0] = w3w[base];
            b3r[nt][ks][1] = w3w[base + 4];
        }
    float bb2[2][2], bb3[2][2];
#pragma unroll
    for (int nt = 0; nt < 2; nt++) {
        bb2[nt][0] = b2[nb2 + nt * 8 + 2 * c];
        bb2[nt][1] = b2[nb2 + nt * 8 + 2 * c + 1];
        bb3[nt][0] = b3[gb3 + nt * 8 + 2 * c];
        bb3[nt][1] = b3[gb3 + nt * 8 + 2 * c + 1];
    }

    // ---- ldmatrix per-lane base addresses ----
    const int tsel = lane >> 3, rr = lane & 7;
    const int lrow = (tsel & 1) * 8 + rr;
    const int lcol = (tsel >> 1) * 4;
    const uint32_t a1base = sb + OFF_H1 + (lrow * S1W + lcol) * 4;
    const uint32_t a2base = sb + OFF_H2 + (lrow * S3W + lcol) * 4;

    // ---- tid0 pop from this half's counter, skipping invalid items ----
    auto pop = [&]() {
        int ww = atomicAdd(&g_work2[half], 1);
        int ll = 0;
        while (ww < MAXW) {
            ll = lengths[ww & (B - 1)];
            if ((ww >> 7) * TILE < ll) break;
            ww = atomicAdd(&g_work2[half], 1);
        }
        spop[0] = ww; spop[1] = ll;
    };

    // ---- L1: 2 -> 64, one point per thread (256 threads = 256 points) ----
    auto do_L1 = [&](int ww, int ll) {
        const int bm = (ww >> 7) * TILE;
        const int rw = min(TILE, ll - bm);
        if (tid < rw) {
            float2 pp = reinterpret_cast<const float2*>(points)[
                (long long)(ww & (B - 1)) * N + bm + tid];
            const float x = pp.x, y = pp.y;
#pragma unroll
            for (int i = 0; i < 32; i++) {
                const int f = 2 * i;
                float v0 = fmaxf(fmaf(x, w1s[f],     fmaf(y, w1s[64 + f],     b1s[f])),     0.0f);
                float v1 = fmaxf(fmaf(x, w1s[f + 1], fmaf(y, w1s[64 + f + 1], b1s[f + 1])), 0.0f);
                h1w[tid * S1W + i] = packh2(v0, v1);   // bank 4*lane+i: conflict-free
            }
        }
    };

    if (tid == 0) pop();
    __syncthreads();
    int w = spop[0], len = spop[1];
    if (w < MAXW) do_L1(w, len);
    __syncthreads();    // h1 ready

    while (w < MAXW) {
        const int bidx   = w & (B - 1);
        const int base_m = (w >> 7) * TILE;
        const int rows   = min(TILE, len - base_m);
        const int mfmax  = (rows + 15) >> 4;

        // ---- phase B: layer 2 (all 128 cols, duplicated across halves) ----
        for (int mf = 0; mf < mfmax; mf++) {
            float acc[2][4];
#pragma unroll
            for (int nt = 0; nt < 2; nt++)
#pragma unroll
                for (int j = 0; j < 4; j++) acc[nt][j] = 0.0f;
#pragma unroll
            for (int ks = 0; ks < 4; ks++) {
                uint32_t a0, a1, a2, a3;
                ldsm4(a0, a1, a2, a3, a1base + (mf * 16 * S1W + ks * 8) * 4);
#pragma unroll
                for (int nt = 0; nt < 2; nt++)
                    mma_f16(acc[nt], a0, a1, a2, a3, b2r[nt][ks][0], b2r[nt][ks][1]);
            }
            const int r0 = mf * 16 + g, r1 = r0 + 8;
#pragma unroll
            for (int nt = 0; nt < 2; nt++) {
                const int cw = wid * 8 + nt * 4 + c;
                h2w[r0 * S3W + cw] = packh2(fmaxf(acc[nt][0] + bb2[nt][0], 0.0f),
                                            fmaxf(acc[nt][1] + bb2[nt][1], 0.0f));
                h2w[r1 * S3W + cw] = packh2(fmaxf(acc[nt][2] + bb2[nt][0], 0.0f),
                                            fmaxf(acc[nt][3] + bb2[nt][1], 0.0f));
            }
        }
        if (tid == 0) pop();
        __syncthreads();    // h2 ready + next item known; L2 done reading h1
        const int wn = spop[0], lenn = spop[1];

        // ---- phase C: layer 3 (this half's 128 cols) + flush ----
        float rm[2][2] = {{0.0f, 0.0f}, {0.0f, 0.0f}};
        for (int mf = 0; mf < mfmax; mf++) {
            float acc[2][4];
#pragma unroll
            for (int nt = 0; nt < 2; nt++)
#pragma unroll
                for (int j = 0; j < 4; j++) acc[nt][j] = 0.0f;
#pragma unroll
            for (int ks = 0; ks < 8; ks++) {
                uint32_t a0, a1, a2, a3;
                ldsm4(a0, a1, a2, a3, a2base + (mf * 16 * S3W + ks * 8) * 4);
#pragma unroll
                for (int nt = 0; nt < 2; nt++)
                    mma_f16(acc[nt], a0, a1, a2, a3, b3r[nt][ks][0], b3r[nt][ks][1]);
            }
            const int r0 = base_m + mf * 16 + g;
            const int r1 = r0 + 8;
            const bool v0 = r0 < len, v1 = r1 < len;
#pragma unroll
            for (int nt = 0; nt < 2; nt++) {
                float x0 = v0 ? fmaxf(acc[nt][0] + bb3[nt][0], 0.0f) : 0.0f;
                float x1 = v0 ? fmaxf(acc[nt][1] + bb3[nt][1], 0.0f) : 0.0f;
                float y0 = v1 ? fmaxf(acc[nt][2] + bb3[nt][0], 0.0f) : 0.0f;
                float y1 = v1 ? fmaxf(acc[nt][3] + bb3[nt][1], 0.0f) : 0.0f;
                rm[nt][0] = fmaxf(rm[nt][0], fmaxf(x0, y0));
                rm[nt][1] = fmaxf(rm[nt][1], fmaxf(x1, y1));
            }
        }
#pragma unroll
        for (int nt = 0; nt < 2; nt++) {
#pragma unroll
            for (int j = 0; j < 2; j++) {
                float v = rm[nt][j];
                v = fmaxf(v, __shfl_xor_sync(0xFFFFFFFFu, v, 4));
                v = fmaxf(v, __shfl_xor_sync(0xFFFFFFFFu, v, 8));
                v = fmaxf(v, __shfl_xor_sync(0xFFFFFFFFu, v, 16));
                if (g == 0)
                    atomicMax(reinterpret_cast<int*>(&g_agg[bidx * F3 + gb3 + nt * 8 + 2 * c + j]),
                              __float_as_int(v));
            }
        }

        // next tile's L1 (h1 free since sync2; C reads only h2)
        if (wn < MAXW) do_L1(wn, lenn);
        w = wn; len = lenn;
        __syncthreads();    // h1(next) ready; all h2 reads done before next B writes
    }
}

__global__ void __launch_bounds__(256)
rho_kernel(const float* __restrict__ r1w, const float* __restrict__ r1b,
           const float* __restrict__ r2w, const float* __restrict__ r2b,
           const float* __restrict__ r3w, const float* __restrict__ r3b,
           float* __restrict__ out)
{
    __shared__ float a[256], z1[256], z2[128];
    const int b   = blockIdx.x;
    const int tid = threadIdx.x;

    a[tid] = g_agg[b * F3 + tid];
    __syncthreads();

    float acc = r1b[tid];
#pragma unroll 4
    for (int k = 0; k < 256; k++) acc = fmaf(a[k], r1w[k * 256 + tid], acc);
    z1[tid] = fmaxf(acc, 0.0f);
    __syncthreads();

    if (tid < 128) {
        float acc2 = r2b[tid];
#pragma unroll 4
        for (int k = 0; k < 256; k++) acc2 = fmaf(z1[k], r2w[k * 128 + tid], acc2);
        z2[tid] = fmaxf(acc2, 0.0f);
    }
    __syncthreads();

    if (tid < 64) {
        float acc3 = r3b[tid];
#pragma unroll 4
        for (int k = 0; k < 128; k++) acc3 = fmaf(z2[k], r3w[k * 64 + tid], acc3);
        out[b * OUT + tid] = acc3;
    }
}

// ---------------- launch ----------------
extern "C" void kernel_launch(void* const* d_in, const int* in_sizes, int n_in,
                              void* d_out, int out_size)
{
    (void)in_sizes; (void)n_in; (void)out_size;
    const float* points = (const float*)d_in[0];
    const int*   lengths= (const int*)  d_in[1];
    const float* w1  = (const float*)d_in[2];
    const float* b1  = (const float*)d_in[3];
    const float* w2  = (const float*)d_in[4];
    const float* b2  = (const float*)d_in[5];
    const float* w3  = (const float*)d_in[6];
    const float* b3  = (const float*)d_in[7];
    const float* r1w = (const float*)d_in[8];
    const float* r1b = (const float*)d_in[9];
    const float* r2w = (const float*)d_in[10];
    const float* r2b = (const float*)d_in[11];
    const float* r3w = (const float*)d_in[12];
    const float* r3b = (const float*)d_in[13];

    cudaFuncSetAttribute(phi_mma_kernel,
                         cudaFuncAttributeMaxDynamicSharedMemorySize, SMEM_TOTAL);

    prep_kernel<<<128, 256>>>(w2, w3);
    phi_mma_kernel<<<GRID, NT, SMEM_TOTAL>>>(points, lengths, w1, b1, b2, b3);
    rho_kernel<<<B, 256>>>(r1w, r1b, r2w, r2b, r3w, r3b, (float*)d_out);
}